// round 1
// baseline (speedup 1.0000x reference)
#include <cuda_runtime.h>

#define Bb   4
#define Nn   50000
#define Kk   128
#define Ss   256
#define KT   16                 // transforms per scoring block
#define PG   1024               // points per scoring block (256 thr * 4 pts)
#define NG   49                 // ceil(Nn / PG)
#define EPSF 1e-5f

// Scratch (no allocations allowed): transforms + deterministic partial error sums
__device__ float g_transforms[Bb * Kk * 16];
__device__ float g_part[Bb * Kk * NG];

__device__ __forceinline__ float warp_sum(float v) {
#pragma unroll
    for (int o = 16; o; o >>= 1) v += __shfl_xor_sync(0xffffffffu, v, o);
    return v;
}

// ---------------------------------------------------------------------------
// Kernel 1: one block per (b,k) hypothesis. Gather S=256 points, weighted
// centroids + covariance H, then Horn quaternion (4x4 Jacobi eigen) -> R, t.
// ---------------------------------------------------------------------------
__global__ void procrustes_kernel(const float* __restrict__ src,
                                  const float* __restrict__ tgt,
                                  const float* __restrict__ wgt,
                                  const int*   __restrict__ sel) {
    int bk = blockIdx.x;
    int b  = bk >> 7;          // / Kk
    int k  = bk & (Kk - 1);
    int s  = threadIdx.x;      // 0..255
    int lane = s & 31, wp = s >> 5;

    int idx = sel[k * Ss + s];
    int pb  = (b * Nn + idx) * 3;
    float sx = src[pb + 0], sy = src[pb + 1], sz = src[pb + 2];
    float tx = tgt[pb + 0], ty = tgt[pb + 1], tz = tgt[pb + 2];
    float ww = wgt[b * Nn + idx];

    __shared__ float red[9 * 8];
    __shared__ float sums[16];

    // ---- phase 1: sumW and weighted centroids (7 reductions) ----
    {
        float v[7] = {ww, ww * sx, ww * sy, ww * sz, ww * tx, ww * ty, ww * tz};
#pragma unroll
        for (int q = 0; q < 7; q++) {
            float r = warp_sum(v[q]);
            if (lane == 0) red[q * 8 + wp] = r;
        }
        __syncthreads();
        if (s < 7) {
            float a = 0.f;
#pragma unroll
            for (int i = 0; i < 8; i++) a += red[s * 8 + i];
            sums[s] = a;
        }
        __syncthreads();
    }
    float invW = 1.0f / (sums[0] + EPSF);
    float scx = sums[1] * invW, scy = sums[2] * invW, scz = sums[3] * invW;
    float tcx = sums[4] * invW, tcy = sums[5] * invW, tcz = sums[6] * invW;
    __syncthreads();   // red reuse

    // ---- phase 2: H_ij = sum w' * src0_i * tgt0_j  (9 reductions) ----
    {
        float ax = sx - scx, ay = sy - scy, az = sz - scz;
        float bx = ww * (tx - tcx), by = ww * (ty - tcy), bz = ww * (tz - tcz);
        float v[9] = {ax * bx, ax * by, ax * bz,
                      ay * bx, ay * by, ay * bz,
                      az * bx, az * by, az * bz};
#pragma unroll
        for (int q = 0; q < 9; q++) {
            float r = warp_sum(v[q]);
            if (lane == 0) red[q * 8 + wp] = r;
        }
        __syncthreads();
        if (s < 9) {
            float a = 0.f;
#pragma unroll
            for (int i = 0; i < 8; i++) a += red[s * 8 + i];
            sums[7 + s] = a * invW;
        }
        __syncthreads();
    }

    if (s == 0) {
        float Sxx = sums[7],  Sxy = sums[8],  Sxz = sums[9];
        float Syx = sums[10], Syy = sums[11], Syz = sums[12];
        float Szx = sums[13], Szy = sums[14], Szz = sums[15];

        // Horn's 4x4 symmetric matrix
        float A[4][4], V[4][4];
        A[0][0] = Sxx + Syy + Szz; A[0][1] = Syz - Szy; A[0][2] = Szx - Sxz; A[0][3] = Sxy - Syx;
        A[1][1] = Sxx - Syy - Szz; A[1][2] = Sxy + Syx; A[1][3] = Szx + Sxz;
        A[2][2] = -Sxx + Syy - Szz; A[2][3] = Syz + Szy;
        A[3][3] = -Sxx - Syy + Szz;
        A[1][0] = A[0][1]; A[2][0] = A[0][2]; A[3][0] = A[0][3];
        A[2][1] = A[1][2]; A[3][1] = A[1][3]; A[3][2] = A[2][3];
#pragma unroll
        for (int i = 0; i < 4; i++)
#pragma unroll
            for (int j = 0; j < 4; j++) V[i][j] = (i == j) ? 1.f : 0.f;

        // Cyclic Jacobi, 10 sweeps (fp32-converged well before that for 4x4)
        for (int sweep = 0; sweep < 10; sweep++) {
#pragma unroll
            for (int p = 0; p < 3; p++) {
#pragma unroll
                for (int q = p + 1; q < 4; q++) {
                    float apq = A[p][q];
                    if (fabsf(apq) > 1e-20f) {
                        float tau = (A[q][q] - A[p][p]) / (2.0f * apq);
                        float tt  = (tau >= 0.f ? 1.f : -1.f) /
                                    (fabsf(tau) + sqrtf(1.f + tau * tau));
                        float c = rsqrtf(1.f + tt * tt);
                        float sn = tt * c;
#pragma unroll
                        for (int m = 0; m < 4; m++) {
                            float amp = A[m][p], amq = A[m][q];
                            A[m][p] = c * amp - sn * amq;
                            A[m][q] = sn * amp + c * amq;
                        }
#pragma unroll
                        for (int m = 0; m < 4; m++) {
                            float apm = A[p][m], aqm = A[q][m];
                            A[p][m] = c * apm - sn * aqm;
                            A[q][m] = sn * apm + c * aqm;
                        }
#pragma unroll
                        for (int m = 0; m < 4; m++) {
                            float vmp = V[m][p], vmq = V[m][q];
                            V[m][p] = c * vmp - sn * vmq;
                            V[m][q] = sn * vmp + c * vmq;
                        }
                    }
                }
            }
        }
        int jb = 0; float lb = A[0][0];
#pragma unroll
        for (int j = 1; j < 4; j++) { if (A[j][j] > lb) { lb = A[j][j]; jb = j; } }
        float qw = V[0][jb], qx = V[1][jb], qy = V[2][jb], qz = V[3][jb];
        float qn = rsqrtf(qw * qw + qx * qx + qy * qy + qz * qz);
        qw *= qn; qx *= qn; qy *= qn; qz *= qn;

        float R00 = 1.f - 2.f * (qy * qy + qz * qz), R01 = 2.f * (qx * qy - qw * qz), R02 = 2.f * (qx * qz + qw * qy);
        float R10 = 2.f * (qx * qy + qw * qz), R11 = 1.f - 2.f * (qx * qx + qz * qz), R12 = 2.f * (qy * qz - qw * qx);
        float R20 = 2.f * (qx * qz - qw * qy), R21 = 2.f * (qy * qz + qw * qx), R22 = 1.f - 2.f * (qx * qx + qy * qy);

        float t0 = tcx - (R00 * scx + R01 * scy + R02 * scz);
        float t1 = tcy - (R10 * scx + R11 * scy + R12 * scz);
        float t2 = tcz - (R20 * scx + R21 * scy + R22 * scz);

        float* T = g_transforms + bk * 16;
        T[0] = R00; T[1] = R01; T[2]  = R02; T[3]  = t0;
        T[4] = R10; T[5] = R11; T[6]  = R12; T[7]  = t1;
        T[8] = R20; T[9] = R21; T[10] = R22; T[11] = t2;
        T[12] = 0.f; T[13] = 0.f; T[14] = 0.f; T[15] = 1.f;
    }
}

// ---------------------------------------------------------------------------
// Kernel 2: scoring. Block = (point-group g, k-tile kt, batch b).
// 4 points cached in registers per thread, 16 transforms per tile via LDS.128.
// Deterministic partial sums into g_part (no atomics).
// ---------------------------------------------------------------------------
__global__ void __launch_bounds__(256, 2)
score_kernel(const float* __restrict__ src,
             const float* __restrict__ tgt,
             const float* __restrict__ wgt) {
    int g = blockIdx.x, kt = blockIdx.y, b = blockIdx.z;
    int tid = threadIdx.x;

    __shared__ float sT[KT * 16];
    int tb = (b * Kk + kt * KT) * 16;
    for (int i = tid; i < KT * 16; i += 256) sT[i] = g_transforms[tb + i];
    __syncthreads();

    float px[4], py[4], pz[4], qx[4], qy[4], qz[4], wv[4];
#pragma unroll
    for (int j = 0; j < 4; j++) {
        int p = g * PG + j * 256 + tid;
        if (p < Nn) {
            int pb = (b * Nn + p) * 3;
            wv[j] = wgt[b * Nn + p];
            px[j] = src[pb + 0]; py[j] = src[pb + 1]; pz[j] = src[pb + 2];
            qx[j] = tgt[pb + 0]; qy[j] = tgt[pb + 1]; qz[j] = tgt[pb + 2];
        } else {
            wv[j] = 0.f;
            px[j] = py[j] = pz[j] = 0.f;
            qx[j] = qy[j] = qz[j] = 0.f;
        }
    }

    float acc[KT];
#pragma unroll
    for (int kk = 0; kk < KT; kk++) acc[kk] = 0.f;

#pragma unroll
    for (int kk = 0; kk < KT; kk++) {
        float4 r0 = *(const float4*)&sT[kk * 16 + 0];
        float4 r1 = *(const float4*)&sT[kk * 16 + 4];
        float4 r2 = *(const float4*)&sT[kk * 16 + 8];
#pragma unroll
        for (int j = 0; j < 4; j++) {
            float dx = fmaf(r0.x, px[j], fmaf(r0.y, py[j], fmaf(r0.z, pz[j], r0.w - qx[j])));
            float dy = fmaf(r1.x, px[j], fmaf(r1.y, py[j], fmaf(r1.z, pz[j], r1.w - qy[j])));
            float dz = fmaf(r2.x, px[j], fmaf(r2.y, py[j], fmaf(r2.z, pz[j], r2.w - qz[j])));
            float d2 = fmaf(dx, dx, fmaf(dy, dy, dz * dz));
            float e;
            asm("sqrt.approx.f32 %0, %1;" : "=f"(e) : "f"(d2));
            acc[kk] = fmaf(wv[j], e, acc[kk]);
        }
    }

    // block-reduce 16 accumulators, write deterministic partials
    __shared__ float red[KT * 8];
    int lane = tid & 31, wp = tid >> 5;
#pragma unroll
    for (int kk = 0; kk < KT; kk++) {
        float v = warp_sum(acc[kk]);
        if (lane == 0) red[kk * 8 + wp] = v;
    }
    __syncthreads();
    if (tid < KT) {
        float s = 0.f;
#pragma unroll
        for (int i = 0; i < 8; i++) s += red[tid * 8 + i];
        g_part[(b * Kk + kt * KT + tid) * NG + g] = s;
    }
}

// ---------------------------------------------------------------------------
// Kernel 3: per-batch argmin over K and emit best 4x4 transform.
// ---------------------------------------------------------------------------
__global__ void pick_kernel(float* __restrict__ out) {
    int b = blockIdx.x;
    int k = threadIdx.x;   // 0..127

    float s = 0.f;
    const float* p = g_part + (b * Kk + k) * NG;
    for (int g = 0; g < NG; g++) s += p[g];

    float best = s; int bi = k;
#pragma unroll
    for (int o = 16; o; o >>= 1) {
        float oe = __shfl_xor_sync(0xffffffffu, best, o);
        int   oi = __shfl_xor_sync(0xffffffffu, bi, o);
        if (oe < best || (oe == best && oi < bi)) { best = oe; bi = oi; }
    }
    __shared__ float wb[4];
    __shared__ int   wi[4];
    __shared__ int   sk;
    int lane = k & 31, wp = k >> 5;
    if (lane == 0) { wb[wp] = best; wi[wp] = bi; }
    __syncthreads();
    if (k == 0) {
        float bb = wb[0]; int ii = wi[0];
#pragma unroll
        for (int i = 1; i < 4; i++)
            if (wb[i] < bb || (wb[i] == bb && wi[i] < ii)) { bb = wb[i]; ii = wi[i]; }
        sk = ii;
    }
    __syncthreads();
    if (k < 16) out[b * 16 + k] = g_transforms[(b * Kk + sk) * 16 + k];
}

// ---------------------------------------------------------------------------
extern "C" void kernel_launch(void* const* d_in, const int* in_sizes, int n_in,
                              void* d_out, int out_size) {
    const float* src = (const float*)d_in[0];   // (B,N,3) f32
    const float* tgt = (const float*)d_in[1];   // (B,N,3) f32
    const float* wgt = (const float*)d_in[2];   // (B,N)   f32
    const int*   sel = (const int*)d_in[3];     // (K,S)   i32
    float* out = (float*)d_out;                 // (B,4,4) f32

    procrustes_kernel<<<Bb * Kk, Ss>>>(src, tgt, wgt, sel);
    dim3 grid2(NG, Kk / KT, Bb);
    score_kernel<<<grid2, 256>>>(src, tgt, wgt);
    pick_kernel<<<Bb, 128>>>(out);
}